// round 1
// baseline (speedup 1.0000x reference)
#include <cuda_runtime.h>
#include <math.h>

#define NN 100000
#define NE 1600000
#define NB 256
#define NO 32
#define HD 128
#define ODIM 32
#define NL 3

// ---------------- device scratch (no allocations allowed) ----------------
__device__ float g_h[NN * HD];
__device__ float g_agg[NN * HD];
__device__ float g_z1[NN * HD];
__device__ float g_z2[NN * HD];
__device__ int   g_rowptr[NN + 1];
__device__ int   g_fill[NN];
__device__ int   g_colsrc[NE];
__device__ float g_stats[2 * HD];
__device__ float g_scale[HD];
__device__ float g_shift[HD];
__device__ float g_graph[NB * 3 * HD];
__device__ int   g_start[NB + 1];
__device__ int   g_bsum[128];

// ---------------- f32x2 helpers ----------------
__device__ __forceinline__ unsigned long long pack2(float x, float y) {
    unsigned long long r;
    asm("mov.b64 %0, {%1,%2};" : "=l"(r) : "f"(x), "f"(y));
    return r;
}
__device__ __forceinline__ void unpack2(unsigned long long v, float& x, float& y) {
    asm("mov.b64 {%0,%1}, %2;" : "=f"(x), "=f"(y) : "l"(v));
}
__device__ __forceinline__ unsigned long long fma2(unsigned long long a, unsigned long long b, unsigned long long c) {
    unsigned long long d;
    asm("fma.rn.f32x2 %0, %1, %2, %3;" : "=l"(d) : "l"(a), "l"(b), "l"(c));
    return d;
}

// ---------------- CSR build ----------------
__global__ void k_hist(const int* __restrict__ ei) {
    int e = blockIdx.x * blockDim.x + threadIdx.x;
    if (e < NE) atomicAdd(&g_rowptr[ei[NE + e] + 1], 1);
}

// inclusive scan over NN+1 elems, chunks of 1024
__global__ void k_scan1() {
    __shared__ int wsum[32];
    int tid = threadIdx.x;
    int gid = blockIdx.x * 1024 + tid;
    int v = (gid <= NN) ? g_rowptr[gid] : 0;
    int lane = tid & 31, wid = tid >> 5;
    int x = v;
#pragma unroll
    for (int d = 1; d < 32; d <<= 1) {
        int y = __shfl_up_sync(0xFFFFFFFFu, x, d);
        if (lane >= d) x += y;
    }
    if (lane == 31) wsum[wid] = x;
    __syncthreads();
    if (wid == 0) {
        int y = wsum[lane];
#pragma unroll
        for (int d = 1; d < 32; d <<= 1) {
            int z = __shfl_up_sync(0xFFFFFFFFu, y, d);
            if (lane >= d) y += z;
        }
        wsum[lane] = y;
    }
    __syncthreads();
    if (wid > 0) x += wsum[wid - 1];
    if (gid <= NN) g_rowptr[gid] = x;
    if (tid == 1023) g_bsum[blockIdx.x] = x;
}

__global__ void k_scan2(int nblocks) {
    if (threadIdx.x == 0) {
        int acc = 0;
        for (int i = 0; i < nblocks; i++) { acc += g_bsum[i]; g_bsum[i] = acc; }
    }
}

__global__ void k_scan3() {
    int gid = blockIdx.x * 1024 + threadIdx.x;
    if (blockIdx.x > 0 && gid <= NN) g_rowptr[gid] += g_bsum[blockIdx.x - 1];
}

__global__ void k_fillcsr(const int* __restrict__ ei) {
    int e = blockIdx.x * blockDim.x + threadIdx.x;
    if (e < NE) {
        int dst = ei[NE + e];
        int pos = g_rowptr[dst] + atomicAdd(&g_fill[dst], 1);
        g_colsrc[pos] = ei[e];
    }
}

// ---------------- aggregation: warp per node, agg[n] = h[n] + sum h[src] ----------------
__global__ void k_agg() {
    int w = (blockIdx.x * blockDim.x + threadIdx.x) >> 5;
    int lane = threadIdx.x & 31;
    if (w >= NN) return;
    const float4* hv = (const float4*)g_h;
    float4 acc = hv[w * 32 + lane];
    int e = g_rowptr[w], eend = g_rowptr[w + 1];
    for (; e + 4 <= eend; e += 4) {
        int s0 = g_colsrc[e + 0], s1 = g_colsrc[e + 1];
        int s2 = g_colsrc[e + 2], s3 = g_colsrc[e + 3];
        float4 v0 = hv[s0 * 32 + lane];
        float4 v1 = hv[s1 * 32 + lane];
        float4 v2 = hv[s2 * 32 + lane];
        float4 v3 = hv[s3 * 32 + lane];
        acc.x += (v0.x + v1.x) + (v2.x + v3.x);
        acc.y += (v0.y + v1.y) + (v2.y + v3.y);
        acc.z += (v0.z + v1.z) + (v2.z + v3.z);
        acc.w += (v0.w + v1.w) + (v2.w + v3.w);
    }
    for (; e < eend; e++) {
        int s = g_colsrc[e];
        float4 v = hv[s * 32 + lane];
        acc.x += v.x; acc.y += v.y; acc.z += v.z; acc.w += v.w;
    }
    ((float4*)g_agg)[w * 32 + lane] = acc;
}

// ---------------- GEMM: C[n,128] = act(A[n,128] @ W[128,128] + bias) ----------------
// 64 rows per block, 256 threads, thread = 4 rows x 8 cols, f32x2 packed FMA.
template <int RELU, int STATS>
__global__ void k_gemm(const float* __restrict__ A, const float* __restrict__ W,
                       const float* __restrict__ bias, float* __restrict__ C, int nrows) {
    extern __shared__ float sh[];
    float* Ws = sh;                 // 128*128
    float* As = sh + 128 * 128;     // 64*132 (padded)
    int tid = threadIdx.x;
    int row0 = blockIdx.x * 64;

    {   // load W (16384 floats = 4096 float4)
        const float4* Wg = (const float4*)W;
        float4* Wsv = (float4*)Ws;
#pragma unroll
        for (int i = 0; i < 16; i++) Wsv[tid + i * 256] = Wg[tid + i * 256];
    }
    {   // load A tile (64x128), pad stride 132
#pragma unroll
        for (int i = 0; i < 8; i++) {
            int idx = tid + i * 256;          // 0..2047
            int r = idx >> 5;
            int c = (idx & 31) << 2;
            int gr = row0 + r;
            float4 v = make_float4(0.f, 0.f, 0.f, 0.f);
            if (gr < nrows) v = *(const float4*)&A[gr * 128 + c];
            *(float4*)&As[r * 132 + c] = v;
        }
    }
    __syncthreads();

    int tcol = tid & 15, trow = tid >> 4;
    int j0 = tcol * 8, r0 = trow * 4;
    unsigned long long acc[4][4];
#pragma unroll
    for (int i = 0; i < 4; i++)
#pragma unroll
        for (int p = 0; p < 4; p++) acc[i][p] = 0ULL;

#pragma unroll 4
    for (int k = 0; k < 128; k++) {
        ulonglong2 wA = *(const ulonglong2*)&Ws[k * 128 + j0];
        ulonglong2 wB = *(const ulonglong2*)&Ws[k * 128 + j0 + 4];
#pragma unroll
        for (int i = 0; i < 4; i++) {
            float a = As[(r0 + i) * 132 + k];
            unsigned long long ap = pack2(a, a);
            acc[i][0] = fma2(ap, wA.x, acc[i][0]);
            acc[i][1] = fma2(ap, wA.y, acc[i][1]);
            acc[i][2] = fma2(ap, wB.x, acc[i][2]);
            acc[i][3] = fma2(ap, wB.y, acc[i][3]);
        }
    }

    float bcol[8];
#pragma unroll
    for (int p = 0; p < 8; p++) bcol[p] = bias[j0 + p];

    float vals[4][8];
#pragma unroll
    for (int i = 0; i < 4; i++) {
#pragma unroll
        for (int p = 0; p < 4; p++) unpack2(acc[i][p], vals[i][2 * p], vals[i][2 * p + 1]);
#pragma unroll
        for (int p = 0; p < 8; p++) {
            float v = vals[i][p] + bcol[p];
            if (RELU) v = fmaxf(v, 0.f);
            vals[i][p] = v;
        }
        int gr = row0 + r0 + i;
        if (gr < nrows) {
            *(float4*)&C[gr * 128 + j0]     = make_float4(vals[i][0], vals[i][1], vals[i][2], vals[i][3]);
            *(float4*)&C[gr * 128 + j0 + 4] = make_float4(vals[i][4], vals[i][5], vals[i][6], vals[i][7]);
        }
    }

    if (STATS) {
        __syncthreads();
        float* redS = As;                 // 16*128
        float* redQ = As + 16 * 128;      // 16*128
#pragma unroll
        for (int p = 0; p < 8; p++) {
            float s = 0.f, q = 0.f;
#pragma unroll
            for (int i = 0; i < 4; i++) {
                if (row0 + r0 + i < nrows) {
                    float v = vals[i][p];
                    s += v; q += v * v;
                }
            }
            redS[trow * 128 + j0 + p] = s;
            redQ[trow * 128 + j0 + p] = q;
        }
        __syncthreads();
        if (tid < 128) {
            float s = 0.f, q = 0.f;
#pragma unroll
            for (int t = 0; t < 16; t++) { s += redS[t * 128 + tid]; q += redQ[t * 128 + tid]; }
            atomicAdd(&g_stats[tid], s);
            atomicAdd(&g_stats[128 + tid], q);
        }
    }
}

__global__ void k_finalize(const float* __restrict__ gamma, const float* __restrict__ beta) {
    int j = threadIdx.x;
    float mu = g_stats[j] * (1.0f / NN);
    float var = g_stats[128 + j] * (1.0f / NN) - mu * mu;
    float a = gamma[j] * rsqrtf(var + 1e-5f);
    g_scale[j] = a;
    g_shift[j] = beta[j] - mu * a;
}

template <int RELU>
__global__ void k_bn() {
    int idx = blockIdx.x * blockDim.x + threadIdx.x;   // per float4
    if (idx >= NN * 32) return;
    int c = (idx & 31) << 2;
    float4 v = ((const float4*)g_z2)[idx];
    float4 s = *(const float4*)&g_scale[c];
    float4 t = *(const float4*)&g_shift[c];
    v.x = v.x * s.x + t.x; v.y = v.y * s.y + t.y;
    v.z = v.z * s.z + t.z; v.w = v.w * s.w + t.w;
    if (RELU) {
        v.x = fmaxf(v.x, 0.f); v.y = fmaxf(v.y, 0.f);
        v.z = fmaxf(v.z, 0.f); v.w = fmaxf(v.w, 0.f);
    }
    ((float4*)g_h)[idx] = v;
}

// ---------------- pooling ----------------
__global__ void k_start(const int* __restrict__ batch) {
    int n = blockIdx.x * blockDim.x + threadIdx.x;
    if (n >= NN) return;
    int b = batch[n];
    if (n == 0) {
        for (int i = 0; i <= b; i++) g_start[i] = 0;
    } else {
        int p = batch[n - 1];
        for (int i = p + 1; i <= b; i++) g_start[i] = n;
    }
    if (n == NN - 1) {
        for (int i = b + 1; i <= NB; i++) g_start[i] = NN;
    }
}

__global__ void k_pool() {
    int b = blockIdx.x, j = threadIdx.x;   // 128 threads
    int s = g_start[b], e = g_start[b + 1];
    float sum = 0.f, mx = -3.402823466e38f;
    int n = s;
    for (; n + 2 <= e; n += 2) {
        float v0 = g_h[n * HD + j];
        float v1 = g_h[(n + 1) * HD + j];
        sum += v0 + v1;
        mx = fmaxf(mx, fmaxf(v0, v1));
    }
    for (; n < e; n++) {
        float v = g_h[n * HD + j];
        sum += v; mx = fmaxf(mx, v);
    }
    int cnt = e - s;
    g_graph[b * 384 + j]       = cnt ? sum / (float)cnt : 0.f;
    g_graph[b * 384 + 128 + j] = cnt ? mx : 0.f;
    g_graph[b * 384 + 256 + j] = sum;
}

// ---------------- head: one block per graph, 32 orders ----------------
__global__ void k_head(const float* __restrict__ orders,
                       const float* __restrict__ oW1, const float* __restrict__ ob1,
                       const float* __restrict__ oW2, const float* __restrict__ ob2,
                       const float* __restrict__ sW1, const float* __restrict__ sb1,
                       const float* __restrict__ sW2, const float* __restrict__ sb2,
                       const float* __restrict__ sW3, const float* __restrict__ sb3,
                       float* __restrict__ out) {
    extern __shared__ float sh[];
    float* comb  = sh;                       // 32*512
    float* t_all = comb + 32 * 512;          // 32*128 (t, then s1)
    float* s2m   = t_all + 32 * 128;         // 32*68
    float* ords  = s2m + 32 * 68;            // 32*33
    int b = blockIdx.x, tid = threadIdx.x;   // 128 threads

    for (int idx = tid; idx < 32 * 384; idx += 128) {
        int o = idx / 384, k = idx - o * 384;
        comb[o * 512 + k] = g_graph[b * 384 + k];
    }
    for (int idx = tid; idx < 32 * 32; idx += 128) {
        int o = idx >> 5, k = idx & 31;
        ords[o * 33 + k] = orders[(b * 32 + o) * 32 + k];
    }
    __syncthreads();

    int tcol = tid & 31, tord = tid >> 5;    // 32 col-groups x 4, 4 ord-groups x 8

    {   // A1: t = relu(ords @ oW1 + ob1)   [32 x 128]
        float4 bc = *(const float4*)&ob1[tcol * 4];
        float acc[8][4];
#pragma unroll
        for (int i = 0; i < 8; i++) { acc[i][0] = bc.x; acc[i][1] = bc.y; acc[i][2] = bc.z; acc[i][3] = bc.w; }
#pragma unroll
        for (int k = 0; k < 32; k++) {
            float4 w = *(const float4*)&oW1[k * 128 + tcol * 4];
#pragma unroll
            for (int i = 0; i < 8; i++) {
                float a = ords[(tord * 8 + i) * 33 + k];
                acc[i][0] += a * w.x; acc[i][1] += a * w.y;
                acc[i][2] += a * w.z; acc[i][3] += a * w.w;
            }
        }
#pragma unroll
        for (int i = 0; i < 8; i++)
            *(float4*)&t_all[(tord * 8 + i) * 128 + tcol * 4] =
                make_float4(fmaxf(acc[i][0], 0.f), fmaxf(acc[i][1], 0.f),
                            fmaxf(acc[i][2], 0.f), fmaxf(acc[i][3], 0.f));
    }
    __syncthreads();

    {   // A2: oe = t @ oW2 + ob2 -> comb[o][384..511]
        float4 bc = *(const float4*)&ob2[tcol * 4];
        float acc[8][4];
#pragma unroll
        for (int i = 0; i < 8; i++) { acc[i][0] = bc.x; acc[i][1] = bc.y; acc[i][2] = bc.z; acc[i][3] = bc.w; }
#pragma unroll 4
        for (int k = 0; k < 128; k++) {
            float4 w = *(const float4*)&oW2[k * 128 + tcol * 4];
#pragma unroll
            for (int i = 0; i < 8; i++) {
                float a = t_all[(tord * 8 + i) * 128 + k];
                acc[i][0] += a * w.x; acc[i][1] += a * w.y;
                acc[i][2] += a * w.z; acc[i][3] += a * w.w;
            }
        }
        __syncthreads();   // everyone done reading t_all before comb writes race with B reading? (B also rewrites t_all)
#pragma unroll
        for (int i = 0; i < 8; i++)
            *(float4*)&comb[(tord * 8 + i) * 512 + 384 + tcol * 4] =
                make_float4(acc[i][0], acc[i][1], acc[i][2], acc[i][3]);
    }
    __syncthreads();

    {   // B: s1 = relu(comb @ sW1 + sb1)  [32 x 128] -> t_all
        float4 bc = *(const float4*)&sb1[tcol * 4];
        float acc[8][4];
#pragma unroll
        for (int i = 0; i < 8; i++) { acc[i][0] = bc.x; acc[i][1] = bc.y; acc[i][2] = bc.z; acc[i][3] = bc.w; }
#pragma unroll 4
        for (int k = 0; k < 512; k++) {
            float4 w = *(const float4*)&sW1[k * 128 + tcol * 4];
#pragma unroll
            for (int i = 0; i < 8; i++) {
                float a = comb[(tord * 8 + i) * 512 + k];
                acc[i][0] += a * w.x; acc[i][1] += a * w.y;
                acc[i][2] += a * w.z; acc[i][3] += a * w.w;
            }
        }
#pragma unroll
        for (int i = 0; i < 8; i++)
            *(float4*)&t_all[(tord * 8 + i) * 128 + tcol * 4] =
                make_float4(fmaxf(acc[i][0], 0.f), fmaxf(acc[i][1], 0.f),
                            fmaxf(acc[i][2], 0.f), fmaxf(acc[i][3], 0.f));
    }
    __syncthreads();

    {   // C: s2 = relu(s1 @ sW2 + sb2)  [32 x 64]
        int tc2 = tid & 15, to2 = tid >> 4;   // 16 col-groups x 4, 8 ord-groups x 4
        float4 bc = *(const float4*)&sb2[tc2 * 4];
        float acc[4][4];
#pragma unroll
        for (int i = 0; i < 4; i++) { acc[i][0] = bc.x; acc[i][1] = bc.y; acc[i][2] = bc.z; acc[i][3] = bc.w; }
#pragma unroll 4
        for (int k = 0; k < 128; k++) {
            float4 w = *(const float4*)&sW2[k * 64 + tc2 * 4];
#pragma unroll
            for (int i = 0; i < 4; i++) {
                float a = t_all[(to2 * 4 + i) * 128 + k];
                acc[i][0] += a * w.x; acc[i][1] += a * w.y;
                acc[i][2] += a * w.z; acc[i][3] += a * w.w;
            }
        }
#pragma unroll
        for (int i = 0; i < 4; i++)
            *(float4*)&s2m[(to2 * 4 + i) * 68 + tc2 * 4] =
                make_float4(fmaxf(acc[i][0], 0.f), fmaxf(acc[i][1], 0.f),
                            fmaxf(acc[i][2], 0.f), fmaxf(acc[i][3], 0.f));
    }
    __syncthreads();

    if (tid < 32) {   // D: out = s2 @ sW3 + sb3
        float acc = sb3[0];
#pragma unroll 8
        for (int k = 0; k < 64; k++) acc += s2m[tid * 68 + k] * sW3[k];
        out[b * 32 + tid] = acc;
    }
}

// ---------------- launch ----------------
extern "C" void kernel_launch(void* const* d_in, const int* in_sizes, int n_in,
                              void* d_out, int out_size) {
    const float* x      = (const float*)d_in[0];
    const int*   ei     = (const int*)d_in[1];
    const float* orders = (const float*)d_in[2];
    const int*   batch  = (const int*)d_in[3];
    const float* gW1    = (const float*)d_in[4];
    const float* gb1    = (const float*)d_in[5];
    const float* gW2    = (const float*)d_in[6];
    const float* gb2    = (const float*)d_in[7];
    const float* gamma  = (const float*)d_in[8];
    const float* beta   = (const float*)d_in[9];
    const float* oW1    = (const float*)d_in[10];
    const float* ob1    = (const float*)d_in[11];
    const float* oW2    = (const float*)d_in[12];
    const float* ob2    = (const float*)d_in[13];
    const float* sW1    = (const float*)d_in[14];
    const float* sb1    = (const float*)d_in[15];
    const float* sW2    = (const float*)d_in[16];
    const float* sb2    = (const float*)d_in[17];
    const float* sW3    = (const float*)d_in[18];
    const float* sb3    = (const float*)d_in[19];
    float* out = (float*)d_out;

    void *p_rowptr, *p_fill, *p_stats, *p_h, *p_agg, *p_z1, *p_z2;
    cudaGetSymbolAddress(&p_rowptr, g_rowptr);
    cudaGetSymbolAddress(&p_fill,   g_fill);
    cudaGetSymbolAddress(&p_stats,  g_stats);
    cudaGetSymbolAddress(&p_h,      g_h);
    cudaGetSymbolAddress(&p_agg,    g_agg);
    cudaGetSymbolAddress(&p_z1,     g_z1);
    cudaGetSymbolAddress(&p_z2,     g_z2);

    size_t gemm_smem = (size_t)(128 * 128 + 64 * 132) * 4;
    size_t head_smem = (size_t)(32 * 512 + 32 * 128 + 32 * 68 + 32 * 33) * 4;
    cudaFuncSetAttribute(k_gemm<1, 0>, cudaFuncAttributeMaxDynamicSharedMemorySize, (int)gemm_smem);
    cudaFuncSetAttribute(k_gemm<0, 1>, cudaFuncAttributeMaxDynamicSharedMemorySize, (int)gemm_smem);
    cudaFuncSetAttribute(k_head, cudaFuncAttributeMaxDynamicSharedMemorySize, (int)head_smem);

    const int SCAN_BLOCKS = (NN + 1 + 1023) / 1024;   // 98

    // CSR build (once per launch, reused by all 3 layers)
    cudaMemsetAsync(p_rowptr, 0, (NN + 1) * sizeof(int));
    cudaMemsetAsync(p_fill,   0, NN * sizeof(int));
    k_hist<<<(NE + 255) / 256, 256>>>(ei);
    k_scan1<<<SCAN_BLOCKS, 1024>>>();
    k_scan2<<<1, 32>>>(SCAN_BLOCKS);
    k_scan3<<<SCAN_BLOCKS, 1024>>>();
    k_fillcsr<<<(NE + 255) / 256, 256>>>(ei);

    // h = x
    cudaMemcpyAsync(p_h, x, (size_t)NN * HD * sizeof(float), cudaMemcpyDeviceToDevice);

    int gemm_grid = (NN + 63) / 64;
    for (int l = 0; l < NL; l++) {
        k_agg<<<(NN * 32 + 255) / 256, 256>>>();
        k_gemm<1, 0><<<gemm_grid, 256, gemm_smem>>>((const float*)p_agg, gW1 + l * HD * HD,
                                                    gb1 + l * HD, (float*)p_z1, NN);
        cudaMemsetAsync(p_stats, 0, 2 * HD * sizeof(float));
        k_gemm<0, 1><<<gemm_grid, 256, gemm_smem>>>((const float*)p_z1, gW2 + l * HD * HD,
                                                    gb2 + l * HD, (float*)p_z2, NN);
        k_finalize<<<1, 128>>>(gamma + l * HD, beta + l * HD);
        if (l < NL - 1) k_bn<1><<<(NN * 32 + 255) / 256, 256>>>();
        else            k_bn<0><<<(NN * 32 + 255) / 256, 256>>>();
    }

    k_start<<<(NN + 255) / 256, 256>>>(batch);
    k_pool<<<NB, 128>>>();
    k_head<<<NB, 128, head_smem>>>(orders, oW1, ob1, oW2, ob2,
                                   sW1, sb1, sW2, sb2, sW3, sb3, out);
}

// round 3
// speedup vs baseline: 1.4634x; 1.4634x over previous
#include <cuda_runtime.h>
#include <cuda_bf16.h>
#include <mma.h>
#include <math.h>
#include <stdint.h>

using namespace nvcuda;

#define NN 100000
#define NE 1600000
#define NB 256
#define HD 128
#define NL 3

#define LDA 136          // bf16 smem stride (A and W tiles)
#define LDSG 132         // f32 staging stride
#define TILE_E (128 * LDA)   // 17408 elements per bf16 tile

// ---------------- device scratch ----------------
__device__ float g_agg[NN * HD];
__device__ float g_z2[NN * HD];
__device__ int   g_rowptr[NN + 1];
__device__ int   g_fill[NN];
__device__ int   g_colsrc[NE];
__device__ float g_stats[2 * HD];
__device__ float g_scale[HD];
__device__ float g_shift[HD];
__device__ float g_graph[NB * 3 * HD];
__device__ int   g_start[NB + 1];
__device__ int   g_bsum[128];
// weight image: per layer [W1hi][W1lo][W2hi][W2lo], each 128x136 bf16 ([k][n] row-major, padded)
__device__ __align__(16) __nv_bfloat16 g_wimg[NL * 4 * TILE_E];

union B8 { uint4 u; __nv_bfloat16 b[8]; };

// ---------------- weight image prep ----------------
__global__ void k_prepw(const float* __restrict__ gW1, const float* __restrict__ gW2) {
    int idx = blockIdx.x * blockDim.x + threadIdx.x;   // NL*2*16384
    if (idx >= NL * 2 * 16384) return;
    int l = idx / 32768;
    int rem = idx - l * 32768;
    int m = rem >> 14;           // 0 = W1, 1 = W2
    int e = rem & 16383;
    int k = e >> 7;
    int n = e & 127;
    float v = (m ? gW2 : gW1)[l * 16384 + k * 128 + n];
    __nv_bfloat16 hi = __float2bfloat16_rn(v);
    __nv_bfloat16 lo = __float2bfloat16_rn(v - __bfloat162float(hi));
    __nv_bfloat16* base = g_wimg + (size_t)(l * 4 + m * 2) * TILE_E;
    base[k * LDA + n] = hi;
    base[TILE_E + k * LDA + n] = lo;
}

// ---------------- CSR build ----------------
__global__ void k_hist(const int* __restrict__ ei) {
    int e = blockIdx.x * blockDim.x + threadIdx.x;
    if (e < NE) atomicAdd(&g_rowptr[ei[NE + e] + 1], 1);
}
__global__ void k_scan1() {
    __shared__ int wsum[32];
    int tid = threadIdx.x;
    int gid = blockIdx.x * 1024 + tid;
    int v = (gid <= NN) ? g_rowptr[gid] : 0;
    int lane = tid & 31, wid = tid >> 5;
    int x = v;
#pragma unroll
    for (int d = 1; d < 32; d <<= 1) { int y = __shfl_up_sync(0xFFFFFFFFu, x, d); if (lane >= d) x += y; }
    if (lane == 31) wsum[wid] = x;
    __syncthreads();
    if (wid == 0) {
        int y = wsum[lane];
#pragma unroll
        for (int d = 1; d < 32; d <<= 1) { int z = __shfl_up_sync(0xFFFFFFFFu, y, d); if (lane >= d) y += z; }
        wsum[lane] = y;
    }
    __syncthreads();
    if (wid > 0) x += wsum[wid - 1];
    if (gid <= NN) g_rowptr[gid] = x;
    if (tid == 1023) g_bsum[blockIdx.x] = x;
}
__global__ void k_scan2(int nblocks) {
    if (threadIdx.x == 0) {
        int acc = 0;
        for (int i = 0; i < nblocks; i++) { acc += g_bsum[i]; g_bsum[i] = acc; }
    }
}
__global__ void k_scan3() {
    int gid = blockIdx.x * 1024 + threadIdx.x;
    if (blockIdx.x > 0 && gid <= NN) g_rowptr[gid] += g_bsum[blockIdx.x - 1];
}
__global__ void k_fillcsr(const int* __restrict__ ei) {
    int e = blockIdx.x * blockDim.x + threadIdx.x;
    if (e < NE) {
        int dst = ei[NE + e];
        int pos = g_rowptr[dst] + atomicAdd(&g_fill[dst], 1);
        g_colsrc[pos] = ei[e];
    }
}

// ---------------- aggregation (warp/node) with fused BN+ReLU on source ----------------
template <int APPLY>
__global__ void k_agg(const float* __restrict__ src) {
    int w = (blockIdx.x * blockDim.x + threadIdx.x) >> 5;
    int lane = threadIdx.x & 31;
    if (w >= NN) return;
    float4 sc, sf;
    if (APPLY) {
        sc = *(const float4*)&g_scale[lane * 4];
        sf = *(const float4*)&g_shift[lane * 4];
    }
    const float4* hv = (const float4*)src;
    float4 self = hv[w * 32 + lane];
    float4 acc;
    if (APPLY) {
        acc.x = fmaxf(self.x * sc.x + sf.x, 0.f);
        acc.y = fmaxf(self.y * sc.y + sf.y, 0.f);
        acc.z = fmaxf(self.z * sc.z + sf.z, 0.f);
        acc.w = fmaxf(self.w * sc.w + sf.w, 0.f);
    } else acc = self;
    int e = g_rowptr[w], eend = g_rowptr[w + 1];
    for (; e + 4 <= eend; e += 4) {
        int s0 = g_colsrc[e + 0], s1 = g_colsrc[e + 1];
        int s2 = g_colsrc[e + 2], s3 = g_colsrc[e + 3];
        float4 v0 = hv[s0 * 32 + lane];
        float4 v1 = hv[s1 * 32 + lane];
        float4 v2 = hv[s2 * 32 + lane];
        float4 v3 = hv[s3 * 32 + lane];
        if (APPLY) {
            v0.x = fmaxf(v0.x * sc.x + sf.x, 0.f); v0.y = fmaxf(v0.y * sc.y + sf.y, 0.f);
            v0.z = fmaxf(v0.z * sc.z + sf.z, 0.f); v0.w = fmaxf(v0.w * sc.w + sf.w, 0.f);
            v1.x = fmaxf(v1.x * sc.x + sf.x, 0.f); v1.y = fmaxf(v1.y * sc.y + sf.y, 0.f);
            v1.z = fmaxf(v1.z * sc.z + sf.z, 0.f); v1.w = fmaxf(v1.w * sc.w + sf.w, 0.f);
            v2.x = fmaxf(v2.x * sc.x + sf.x, 0.f); v2.y = fmaxf(v2.y * sc.y + sf.y, 0.f);
            v2.z = fmaxf(v2.z * sc.z + sf.z, 0.f); v2.w = fmaxf(v2.w * sc.w + sf.w, 0.f);
            v3.x = fmaxf(v3.x * sc.x + sf.x, 0.f); v3.y = fmaxf(v3.y * sc.y + sf.y, 0.f);
            v3.z = fmaxf(v3.z * sc.z + sf.z, 0.f); v3.w = fmaxf(v3.w * sc.w + sf.w, 0.f);
        }
        acc.x += (v0.x + v1.x) + (v2.x + v3.x);
        acc.y += (v0.y + v1.y) + (v2.y + v3.y);
        acc.z += (v0.z + v1.z) + (v2.z + v3.z);
        acc.w += (v0.w + v1.w) + (v2.w + v3.w);
    }
    for (; e < eend; e++) {
        int s = g_colsrc[e];
        float4 v = hv[s * 32 + lane];
        if (APPLY) {
            v.x = fmaxf(v.x * sc.x + sf.x, 0.f); v.y = fmaxf(v.y * sc.y + sf.y, 0.f);
            v.z = fmaxf(v.z * sc.z + sf.z, 0.f); v.w = fmaxf(v.w * sc.w + sf.w, 0.f);
        }
        acc.x += v.x; acc.y += v.y; acc.z += v.z; acc.w += v.w;
    }
    ((float4*)g_agg)[w * 32 + lane] = acc;
}

// ---------------- fused double GEMM (wmma bf16 3-term split) ----------------
typedef wmma::fragment<wmma::matrix_a, 16, 16, 16, __nv_bfloat16, wmma::row_major> FragA;
typedef wmma::fragment<wmma::matrix_b, 16, 16, 16, __nv_bfloat16, wmma::row_major> FragB;
typedef wmma::fragment<wmma::accumulator, 16, 16, 16, float> FragC;

__device__ __forceinline__ void gemm_pass(const __nv_bfloat16* Ahi, const __nv_bfloat16* Alo,
                                          const __nv_bfloat16* Whi, const __nv_bfloat16* Wlo,
                                          FragC c[2][4], int wy, int wx) {
#pragma unroll
    for (int i = 0; i < 2; i++)
#pragma unroll
        for (int j = 0; j < 4; j++) wmma::fill_fragment(c[i][j], 0.f);
#pragma unroll
    for (int kk = 0; kk < 8; kk++) {
        FragA ahi[2], alo[2];
#pragma unroll
        for (int i = 0; i < 2; i++) {
            wmma::load_matrix_sync(ahi[i], Ahi + (wy * 32 + i * 16) * LDA + kk * 16, LDA);
            wmma::load_matrix_sync(alo[i], Alo + (wy * 32 + i * 16) * LDA + kk * 16, LDA);
        }
#pragma unroll
        for (int j = 0; j < 4; j++) {
            FragB bhi, blo;
            wmma::load_matrix_sync(bhi, Whi + kk * 16 * LDA + wx * 64 + j * 16, LDA);
            wmma::load_matrix_sync(blo, Wlo + kk * 16 * LDA + wx * 64 + j * 16, LDA);
#pragma unroll
            for (int i = 0; i < 2; i++) {
                wmma::mma_sync(c[i][j], ahi[i], bhi, c[i][j]);
                wmma::mma_sync(c[i][j], ahi[i], blo, c[i][j]);
                wmma::mma_sync(c[i][j], alo[i], bhi, c[i][j]);
            }
        }
    }
}

// smem: Ahi(34816) + Alo(34816) + W(4*34816) + stats(1024) = 209920 bytes
#define FG_SMEM (2 * TILE_E * 2 + 4 * TILE_E * 2 + 1024)

__global__ void __launch_bounds__(256, 1)
k_fgemm(const float* __restrict__ A, const __nv_bfloat16* __restrict__ wimg,
        const float* __restrict__ b1, const float* __restrict__ b2,
        float* __restrict__ Z2) {
    extern __shared__ char sh[];
    __nv_bfloat16* Ahi = (__nv_bfloat16*)sh;
    __nv_bfloat16* Alo = Ahi + TILE_E;
    __nv_bfloat16* Wt  = Alo + TILE_E;                    // 4 tiles
    float* stg = (float*)Wt;                              // overlaps W1hi+W1lo (69632 >= 67584)
    float* ss  = (float*)(sh + 2 * TILE_E * 2 + 4 * TILE_E * 2);
    int tid = threadIdx.x;
    int row0 = blockIdx.x * 128;
    int live = NN - row0; if (live > 128) live = 128;

    ss[tid] = 0.f;

    {   // copy weight image (8704 uint4)
        const uint4* wg = (const uint4*)wimg;
        uint4* wd = (uint4*)Wt;
#pragma unroll
        for (int i = 0; i < 34; i++) {
            int idx = tid + i * 256;
            if (idx < 8704) wd[idx] = wg[idx];
        }
    }
    {   // load & split A tile
        for (int i = tid; i < 2048; i += 256) {
            int r = i >> 4, c0 = (i & 15) << 3;
            float v[8];
            if (r < live) {
                float4 p = *(const float4*)&A[(size_t)(row0 + r) * 128 + c0];
                float4 q = *(const float4*)&A[(size_t)(row0 + r) * 128 + c0 + 4];
                v[0] = p.x; v[1] = p.y; v[2] = p.z; v[3] = p.w;
                v[4] = q.x; v[5] = q.y; v[6] = q.z; v[7] = q.w;
            } else {
#pragma unroll
                for (int e = 0; e < 8; e++) v[e] = 0.f;
            }
            B8 hi, lo;
#pragma unroll
            for (int e = 0; e < 8; e++) {
                __nv_bfloat16 h = __float2bfloat16_rn(v[e]);
                hi.b[e] = h;
                lo.b[e] = __float2bfloat16_rn(v[e] - __bfloat162float(h));
            }
            *(uint4*)&Ahi[r * LDA + c0] = hi.u;
            *(uint4*)&Alo[r * LDA + c0] = lo.u;
        }
    }
    __syncthreads();

    int w = tid >> 5, wy = w >> 1, wx = w & 1;
    FragC c[2][4];

    // GEMM1: z1raw = A @ W1
    gemm_pass(Ahi, Alo, Wt, Wt + TILE_E, c, wy, wx);
    __syncthreads();   // all warps done reading W1 before staging overwrite
#pragma unroll
    for (int i = 0; i < 2; i++)
#pragma unroll
        for (int j = 0; j < 4; j++)
            wmma::store_matrix_sync(stg + (wy * 32 + i * 16) * LDSG + wx * 64 + j * 16,
                                    c[i][j], LDSG, wmma::mem_row_major);
    __syncthreads();

    // z1 = relu(z1raw + b1) -> split -> Ahi/Alo
    for (int i = tid; i < 2048; i += 256) {
        int r = i >> 4, c0 = (i & 15) << 3;
        B8 hi, lo;
#pragma unroll
        for (int e = 0; e < 8; e++) {
            float v = fmaxf(stg[r * LDSG + c0 + e] + b1[c0 + e], 0.f);
            __nv_bfloat16 h = __float2bfloat16_rn(v);
            hi.b[e] = h;
            lo.b[e] = __float2bfloat16_rn(v - __bfloat162float(h));
        }
        *(uint4*)&Ahi[r * LDA + c0] = hi.u;
        *(uint4*)&Alo[r * LDA + c0] = lo.u;
    }
    __syncthreads();

    // GEMM2: z2raw = z1 @ W2
    gemm_pass(Ahi, Alo, Wt + 2 * TILE_E, Wt + 3 * TILE_E, c, wy, wx);
    __syncthreads();
#pragma unroll
    for (int i = 0; i < 2; i++)
#pragma unroll
        for (int j = 0; j < 4; j++)
            wmma::store_matrix_sync(stg + (wy * 32 + i * 16) * LDSG + wx * 64 + j * 16,
                                    c[i][j], LDSG, wmma::mem_row_major);
    __syncthreads();

    {   // row pass: z2 = z2raw + b2 -> global
        int r = tid >> 1, h = tid & 1;
        if (r < live) {
            int c0 = h * 64;
#pragma unroll
            for (int g = 0; g < 16; g++) {
                float4 v;
                v.x = stg[r * LDSG + c0 + g * 4 + 0] + b2[c0 + g * 4 + 0];
                v.y = stg[r * LDSG + c0 + g * 4 + 1] + b2[c0 + g * 4 + 1];
                v.z = stg[r * LDSG + c0 + g * 4 + 2] + b2[c0 + g * 4 + 2];
                v.w = stg[r * LDSG + c0 + g * 4 + 3] + b2[c0 + g * 4 + 3];
                *(float4*)&Z2[(size_t)(row0 + r) * 128 + c0 + g * 4] = v;
            }
        }
    }
    {   // col pass: stats
        int cc = tid & 127, h = tid >> 7;
        float bias = b2[cc];
        float s = 0.f, q = 0.f;
        for (int r = h; r < live; r += 2) {
            float v = stg[r * LDSG + cc] + bias;
            s += v; q += v * v;
        }
        atomicAdd(&ss[cc], s);
        atomicAdd(&ss[128 + cc], q);
    }
    __syncthreads();
    if (tid < 128) {
        atomicAdd(&g_stats[tid], ss[tid]);
        atomicAdd(&g_stats[128 + tid], ss[128 + tid]);
    }
}

__global__ void k_finalize(const float* __restrict__ gamma, const float* __restrict__ beta) {
    int j = threadIdx.x;
    float mu = g_stats[j] * (1.0f / NN);
    float var = g_stats[128 + j] * (1.0f / NN) - mu * mu;
    float a = gamma[j] * rsqrtf(var + 1e-5f);
    g_scale[j] = a;
    g_shift[j] = beta[j] - mu * a;
}

// ---------------- pooling (applies final BN, no relu) ----------------
__global__ void k_start(const int* __restrict__ batch) {
    int n = blockIdx.x * blockDim.x + threadIdx.x;
    if (n >= NN) return;
    int b = batch[n];
    if (n == 0) { for (int i = 0; i <= b; i++) g_start[i] = 0; }
    else {
        int p = batch[n - 1];
        for (int i = p + 1; i <= b; i++) g_start[i] = n;
    }
    if (n == NN - 1) { for (int i = b + 1; i <= NB; i++) g_start[i] = NN; }
}

__global__ void k_pool() {
    int b = blockIdx.x, j = threadIdx.x;   // 128 threads
    int s = g_start[b], e = g_start[b + 1];
    float sc = g_scale[j], sf = g_shift[j];
    float sum = 0.f, mx = -3.402823466e38f;
    int n = s;
    for (; n + 2 <= e; n += 2) {
        float v0 = g_z2[(size_t)n * HD + j] * sc + sf;
        float v1 = g_z2[(size_t)(n + 1) * HD + j] * sc + sf;
        sum += v0 + v1;
        mx = fmaxf(mx, fmaxf(v0, v1));
    }
    for (; n < e; n++) {
        float v = g_z2[(size_t)n * HD + j] * sc + sf;
        sum += v; mx = fmaxf(mx, v);
    }
    int cnt = e - s;
    g_graph[b * 384 + j]       = cnt ? sum / (float)cnt : 0.f;
    g_graph[b * 384 + 128 + j] = cnt ? mx : 0.f;
    g_graph[b * 384 + 256 + j] = sum;
}

// ---------------- head ----------------
__global__ void k_head(const float* __restrict__ orders,
                       const float* __restrict__ oW1, const float* __restrict__ ob1,
                       const float* __restrict__ oW2, const float* __restrict__ ob2,
                       const float* __restrict__ sW1, const float* __restrict__ sb1,
                       const float* __restrict__ sW2, const float* __restrict__ sb2,
                       const float* __restrict__ sW3, const float* __restrict__ sb3,
                       float* __restrict__ out) {
    extern __shared__ float fsh[];
    float* comb  = fsh;                      // 32*512
    float* t_all = comb + 32 * 512;          // 32*128
    float* s2m   = t_all + 32 * 128;         // 32*68
    float* ords  = s2m + 32 * 68;            // 32*33
    int b = blockIdx.x, tid = threadIdx.x;   // 128 threads

    for (int idx = tid; idx < 32 * 384; idx += 128) {
        int o = idx / 384, k = idx - o * 384;
        comb[o * 512 + k] = g_graph[b * 384 + k];
    }
    for (int idx = tid; idx < 32 * 32; idx += 128) {
        int o = idx >> 5, k = idx & 31;
        ords[o * 33 + k] = orders[(b * 32 + o) * 32 + k];
    }
    __syncthreads();

    int tcol = tid & 31, tord = tid >> 5;

    {   // t = relu(ords @ oW1 + ob1)
        float4 bc = *(const float4*)&ob1[tcol * 4];
        float acc[8][4];
#pragma unroll
        for (int i = 0; i < 8; i++) { acc[i][0] = bc.x; acc[i][1] = bc.y; acc[i][2] = bc.z; acc[i][3] = bc.w; }
#pragma unroll
        for (int k = 0; k < 32; k++) {
            float4 w = *(const float4*)&oW1[k * 128 + tcol * 4];
#pragma unroll
            for (int i = 0; i < 8; i++) {
                float a = ords[(tord * 8 + i) * 33 + k];
                acc[i][0] += a * w.x; acc[i][1] += a * w.y;
                acc[i][2] += a * w.z; acc[i][3] += a * w.w;
            }
        }
#pragma unroll
        for (int i = 0; i < 8; i++)
            *(float4*)&t_all[(tord * 8 + i) * 128 + tcol * 4] =
                make_float4(fmaxf(acc[i][0], 0.f), fmaxf(acc[i][1], 0.f),
                            fmaxf(acc[i][2], 0.f), fmaxf(acc[i][3], 0.f));
    }
    __syncthreads();

    {   // oe = t @ oW2 + ob2 -> comb[:,384:]
        float4 bc = *(const float4*)&ob2[tcol * 4];
        float acc[8][4];
#pragma unroll
        for (int i = 0; i < 8; i++) { acc[i][0] = bc.x; acc[i][1] = bc.y; acc[i][2] = bc.z; acc[i][3] = bc.w; }
#pragma unroll 4
        for (int k = 0; k < 128; k++) {
            float4 w = *(const float4*)&oW2[k * 128 + tcol * 4];
#pragma unroll
            for (int i = 0; i < 8; i++) {
                float a = t_all[(tord * 8 + i) * 128 + k];
                acc[i][0] += a * w.x; acc[i][1] += a * w.y;
                acc[i][2] += a * w.z; acc[i][3] += a * w.w;
            }
        }
        __syncthreads();
#pragma unroll
        for (int i = 0; i < 8; i++)
            *(float4*)&comb[(tord * 8 + i) * 512 + 384 + tcol * 4] =
                make_float4(acc[i][0], acc[i][1], acc[i][2], acc[i][3]);
    }
    __syncthreads();

    {   // s1 = relu(comb @ sW1 + sb1)
        float4 bc = *(const float4*)&sb1[tcol * 4];
        float acc[8][4];
#pragma unroll
        for (int i = 0; i < 8; i++) { acc[i][0] = bc.x; acc[i][1] = bc.y; acc[i][2] = bc.z; acc[i][3] = bc.w; }
#pragma unroll 4
        for (int k = 0; k < 512; k++) {
            float4 w = *(const float4*)&sW1[k * 128 + tcol * 4];
#pragma unroll
            for (int i = 0; i < 8; i++) {
                float a = comb[(tord * 8 + i) * 512 + k];
                acc[i][0] += a * w.x; acc[i][1] += a * w.y;
                acc[i][2] += a * w.z; acc[i][3] += a * w.w;
            }
        }
#pragma unroll
        for (int i = 0; i < 8; i++)
            *(float4*)&t_all[(tord * 8 + i) * 128 + tcol * 4] =
                make_float4(fmaxf(acc[i][0], 0.f), fmaxf(acc[i][1], 0.f),
                            fmaxf(acc[i][2], 0.f), fmaxf(acc[i][3], 0.f));
    }
    __syncthreads();

    {   // s2 = relu(s1 @ sW2 + sb2)
        int tc2 = tid & 15, to2 = tid >> 4;
        float4 bc = *(const float4*)&sb2[tc2 * 4];
        float acc[4][4];
#pragma unroll
        for (int i = 0; i < 4; i++) { acc[i][0] = bc.x; acc[i][1] = bc.y; acc[i][2] = bc.z; acc[i][3] = bc.w; }
#pragma unroll 4
        for (int k = 0; k < 128; k++) {
            float4 w = *(const float4*)&sW2[k * 64 + tc2 * 4];
#pragma unroll
            for (int i = 0; i < 4; i++) {
                float a = t_all[(to2 * 4 + i) * 128 + k];
                acc[i][0] += a * w.x; acc[i][1] += a * w.y;
                acc[i][2] += a * w.z; acc[i][3] += a * w.w;
            }
        }
#pragma unroll
        for (int i = 0; i < 4; i++)
            *(float4*)&s2m[(to2 * 4 + i) * 68 + tc2 * 4] =
                make_float4(fmaxf(acc[i][0], 0.f), fmaxf(acc[i][1], 0.f),
                            fmaxf(acc[i][2], 0.f), fmaxf(acc[i][3], 0.f));
    }
    __syncthreads();

    if (tid < 32) {
        float acc = sb3[0];
#pragma unroll 8
        for (int k = 0; k < 64; k++) acc += s2m[tid * 68 + k] * sW3[k];
        out[b * 32 + tid] = acc;
    }
}

// ---------------- launch ----------------
extern "C" void kernel_launch(void* const* d_in, const int* in_sizes, int n_in,
                              void* d_out, int out_size) {
    const float* x      = (const float*)d_in[0];
    const int*   ei     = (const int*)d_in[1];
    const float* orders = (const float*)d_in[2];
    const int*   batch  = (const int*)d_in[3];
    const float* gW1    = (const float*)d_in[4];
    const float* gb1    = (const float*)d_in[5];
    const float* gW2    = (const float*)d_in[6];
    const float* gb2    = (const float*)d_in[7];
    const float* gamma  = (const float*)d_in[8];
    const float* beta   = (const float*)d_in[9];
    const float* oW1    = (const float*)d_in[10];
    const float* ob1    = (const float*)d_in[11];
    const float* oW2    = (const float*)d_in[12];
    const float* ob2    = (const float*)d_in[13];
    const float* sW1    = (const float*)d_in[14];
    const float* sb1    = (const float*)d_in[15];
    const float* sW2    = (const float*)d_in[16];
    const float* sb2    = (const float*)d_in[17];
    const float* sW3    = (const float*)d_in[18];
    const float* sb3    = (const float*)d_in[19];
    float* out = (float*)d_out;

    void *p_rowptr, *p_fill, *p_stats, *p_agg, *p_z2, *p_wimg;
    cudaGetSymbolAddress(&p_rowptr, g_rowptr);
    cudaGetSymbolAddress(&p_fill,   g_fill);
    cudaGetSymbolAddress(&p_stats,  g_stats);
    cudaGetSymbolAddress(&p_agg,    g_agg);
    cudaGetSymbolAddress(&p_z2,     g_z2);
    cudaGetSymbolAddress(&p_wimg,   g_wimg);

    size_t head_smem = (size_t)(32 * 512 + 32 * 128 + 32 * 68 + 32 * 33) * 4;
    cudaFuncSetAttribute(k_head, cudaFuncAttributeMaxDynamicSharedMemorySize, (int)head_smem);
    cudaFuncSetAttribute(k_fgemm, cudaFuncAttributeMaxDynamicSharedMemorySize, FG_SMEM);

    const int SCAN_BLOCKS = (NN + 1 + 1023) / 1024;

    // weight images + CSR build
    k_prepw<<<(NL * 2 * 16384 + 255) / 256, 256>>>(gW1, gW2);
    cudaMemsetAsync(p_rowptr, 0, (NN + 1) * sizeof(int));
    cudaMemsetAsync(p_fill,   0, NN * sizeof(int));
    k_hist<<<(NE + 255) / 256, 256>>>(ei);
    k_scan1<<<SCAN_BLOCKS, 1024>>>();
    k_scan2<<<1, 32>>>(SCAN_BLOCKS);
    k_scan3<<<SCAN_BLOCKS, 1024>>>();
    k_fillcsr<<<(NE + 255) / 256, 256>>>(ei);

    int fg_grid = (NN + 127) / 128;
    for (int l = 0; l < NL; l++) {
        if (l == 0) k_agg<0><<<(NN * 32 + 255) / 256, 256>>>(x);
        else        k_agg<1><<<(NN * 32 + 255) / 256, 256>>>((const float*)p_z2);
        cudaMemsetAsync(p_stats, 0, 2 * HD * sizeof(float));
        k_fgemm<<<fg_grid, 256, FG_SMEM>>>((const float*)p_agg,
                                           (const __nv_bfloat16*)p_wimg + (size_t)l * 4 * TILE_E,
                                           gb1 + l * HD, gb2 + l * HD, (float*)p_z2);
        k_finalize<<<1, 128>>>(gamma + l * HD, beta + l * HD);
    }

    k_start<<<(NN + 255) / 256, 256>>>(batch);
    k_pool<<<NB, 128>>>();
    k_head<<<NB, 128, head_smem>>>(orders, oW1, ob1, oW2, ob2,
                                   sW1, sb1, sW2, sb2, sW3, sb3, out);
}

// round 4
// speedup vs baseline: 1.4884x; 1.0171x over previous
#include <cuda_runtime.h>
#include <cuda_bf16.h>
#include <mma.h>
#include <math.h>
#include <stdint.h>

using namespace nvcuda;

#define NN 100000
#define NE 1600000
#define NB 256
#define HD 128
#define NL 3

#define TR 64                 // fgemm tile rows
#define NTILES ((NN + TR - 1) / TR)   // 1563
#define LDA 136               // bf16 smem stride
#define LDSG 132              // f32 staging stride
#define TILE_E (128 * LDA)    // elements per 128x136 bf16 weight tile

// ---------------- device scratch ----------------
__device__ float g_agg[NN * HD];
__device__ float g_z2[NN * HD];
__device__ int   g_rowptr[NN + 1];
__device__ int   g_fill[NN];
__device__ int   g_colsrc[NE];
__device__ float g_stats[2 * HD];
__device__ float g_scale[HD];
__device__ float g_shift[HD];
__device__ float g_graph[NB * 3 * HD];
__device__ int   g_start[NB + 1];
__device__ int   g_ticket;
// weight image: per layer [W1hi][W1lo][W2hi][W2lo], each 128x136 bf16 ([k][n] row-major)
__device__ __align__(16) __nv_bfloat16 g_wimg[NL * 4 * TILE_E];

union B8 { uint4 u; __nv_bfloat16 b[8]; };

// ---------------- init / weight prep ----------------
__global__ void k_zero() {
    int i = blockIdx.x * blockDim.x + threadIdx.x;
    if (i <= NN) g_rowptr[i] = 0;
    if (i < NN)  g_fill[i] = 0;
    if (i < 2 * HD) g_stats[i] = 0.f;
    if (i == 0) g_ticket = 0;
}

__global__ void k_prepw(const float* __restrict__ gW1, const float* __restrict__ gW2) {
    int idx = blockIdx.x * blockDim.x + threadIdx.x;
    if (idx >= NL * 2 * 16384) return;
    int l = idx / 32768;
    int rem = idx - l * 32768;
    int m = rem >> 14;
    int e = rem & 16383;
    int k = e >> 7;
    int n = e & 127;
    float v = (m ? gW2 : gW1)[l * 16384 + k * 128 + n];
    __nv_bfloat16 hi = __float2bfloat16_rn(v);
    __nv_bfloat16 lo = __float2bfloat16_rn(v - __bfloat162float(hi));
    __nv_bfloat16* base = g_wimg + (size_t)(l * 4 + m * 2) * TILE_E;
    base[k * LDA + n] = hi;
    base[TILE_E + k * LDA + n] = lo;
}

// ---------------- CSR build ----------------
__global__ void k_hist(const int* __restrict__ ei) {
    int e = blockIdx.x * blockDim.x + threadIdx.x;
    if (e < NE) atomicAdd(&g_rowptr[ei[NE + e] + 1], 1);
}

// single-block inclusive scan over NN+1 elems, chunked 1024, prefetch next chunk
__global__ void k_scan() {
    __shared__ int wsum[32];
    __shared__ int carry;
    int tid = threadIdx.x, lane = tid & 31, wid = tid >> 5;
    if (tid == 0) carry = 0;
    const int NCH = (NN + 1 + 1023) / 1024;   // 98
    int nv = g_rowptr[tid];                   // chunk 0 (tid <= NN always)
    __syncthreads();
    for (int ch = 0; ch < NCH; ch++) {
        int v = nv;
        if (ch + 1 < NCH) {
            int gn = (ch + 1) * 1024 + tid;
            nv = (gn <= NN) ? g_rowptr[gn] : 0;
        }
        int x = v;
#pragma unroll
        for (int d = 1; d < 32; d <<= 1) { int y = __shfl_up_sync(0xFFFFFFFFu, x, d); if (lane >= d) x += y; }
        if (lane == 31) wsum[wid] = x;
        __syncthreads();
        if (wid == 0) {
            int y = wsum[lane];
#pragma unroll
            for (int d = 1; d < 32; d <<= 1) { int z = __shfl_up_sync(0xFFFFFFFFu, y, d); if (lane >= d) y += z; }
            wsum[lane] = y;
        }
        __syncthreads();
        if (wid > 0) x += wsum[wid - 1];
        int out = x + carry;
        int gid = ch * 1024 + tid;
        if (gid <= NN) g_rowptr[gid] = out;
        __syncthreads();
        if (tid == 1023) carry = out;
        __syncthreads();
    }
}

__global__ void k_fillcsr(const int* __restrict__ ei) {
    int e = blockIdx.x * blockDim.x + threadIdx.x;
    if (e < NE) {
        int dst = ei[NE + e];
        int pos = g_rowptr[dst] + atomicAdd(&g_fill[dst], 1);
        g_colsrc[pos] = ei[e];
    }
}

// ---------------- aggregation (warp/node) with fused BN+ReLU on source ----------------
template <int APPLY>
__global__ void k_agg(const float* __restrict__ src) {
    int w = (blockIdx.x * blockDim.x + threadIdx.x) >> 5;
    int lane = threadIdx.x & 31;
    if (w >= NN) return;
    float4 sc, sf;
    if (APPLY) {
        sc = *(const float4*)&g_scale[lane * 4];
        sf = *(const float4*)&g_shift[lane * 4];
    }
    const float4* hv = (const float4*)src;
    float4 self = hv[w * 32 + lane];
    float4 acc;
    if (APPLY) {
        acc.x = fmaxf(self.x * sc.x + sf.x, 0.f);
        acc.y = fmaxf(self.y * sc.y + sf.y, 0.f);
        acc.z = fmaxf(self.z * sc.z + sf.z, 0.f);
        acc.w = fmaxf(self.w * sc.w + sf.w, 0.f);
    } else acc = self;
    int e = g_rowptr[w], eend = g_rowptr[w + 1];
    for (; e + 4 <= eend; e += 4) {
        int s0 = g_colsrc[e + 0], s1 = g_colsrc[e + 1];
        int s2 = g_colsrc[e + 2], s3 = g_colsrc[e + 3];
        float4 v0 = hv[s0 * 32 + lane];
        float4 v1 = hv[s1 * 32 + lane];
        float4 v2 = hv[s2 * 32 + lane];
        float4 v3 = hv[s3 * 32 + lane];
        if (APPLY) {
            v0.x = fmaxf(v0.x * sc.x + sf.x, 0.f); v0.y = fmaxf(v0.y * sc.y + sf.y, 0.f);
            v0.z = fmaxf(v0.z * sc.z + sf.z, 0.f); v0.w = fmaxf(v0.w * sc.w + sf.w, 0.f);
            v1.x = fmaxf(v1.x * sc.x + sf.x, 0.f); v1.y = fmaxf(v1.y * sc.y + sf.y, 0.f);
            v1.z = fmaxf(v1.z * sc.z + sf.z, 0.f); v1.w = fmaxf(v1.w * sc.w + sf.w, 0.f);
            v2.x = fmaxf(v2.x * sc.x + sf.x, 0.f); v2.y = fmaxf(v2.y * sc.y + sf.y, 0.f);
            v2.z = fmaxf(v2.z * sc.z + sf.z, 0.f); v2.w = fmaxf(v2.w * sc.w + sf.w, 0.f);
            v3.x = fmaxf(v3.x * sc.x + sf.x, 0.f); v3.y = fmaxf(v3.y * sc.y + sf.y, 0.f);
            v3.z = fmaxf(v3.z * sc.z + sf.z, 0.f); v3.w = fmaxf(v3.w * sc.w + sf.w, 0.f);
        }
        acc.x += (v0.x + v1.x) + (v2.x + v3.x);
        acc.y += (v0.y + v1.y) + (v2.y + v3.y);
        acc.z += (v0.z + v1.z) + (v2.z + v3.z);
        acc.w += (v0.w + v1.w) + (v2.w + v3.w);
    }
    for (; e < eend; e++) {
        int s = g_colsrc[e];
        float4 v = hv[s * 32 + lane];
        if (APPLY) {
            v.x = fmaxf(v.x * sc.x + sf.x, 0.f); v.y = fmaxf(v.y * sc.y + sf.y, 0.f);
            v.z = fmaxf(v.z * sc.z + sf.z, 0.f); v.w = fmaxf(v.w * sc.w + sf.w, 0.f);
        }
        acc.x += v.x; acc.y += v.y; acc.z += v.z; acc.w += v.w;
    }
    ((float4*)g_agg)[w * 32 + lane] = acc;
}

// ---------------- persistent fused double GEMM (wmma bf16 3-term split) ----------------
typedef wmma::fragment<wmma::matrix_a, 16, 16, 16, __nv_bfloat16, wmma::row_major> FragA;
typedef wmma::fragment<wmma::matrix_b, 16, 16, 16, __nv_bfloat16, wmma::row_major> FragB;
typedef wmma::fragment<wmma::accumulator, 16, 16, 16, float> FragC;

__device__ __forceinline__ void gemm_pass64(const __nv_bfloat16* Ahi, const __nv_bfloat16* Alo,
                                            const __nv_bfloat16* Whi, const __nv_bfloat16* Wlo,
                                            FragC c[2][2], int wy, int wx) {
#pragma unroll
    for (int i = 0; i < 2; i++)
#pragma unroll
        for (int j = 0; j < 2; j++) wmma::fill_fragment(c[i][j], 0.f);
#pragma unroll
    for (int kk = 0; kk < 8; kk++) {
        FragA ahi[2], alo[2];
#pragma unroll
        for (int i = 0; i < 2; i++) {
            wmma::load_matrix_sync(ahi[i], Ahi + (wy * 32 + i * 16) * LDA + kk * 16, LDA);
            wmma::load_matrix_sync(alo[i], Alo + (wy * 32 + i * 16) * LDA + kk * 16, LDA);
        }
#pragma unroll
        for (int j = 0; j < 2; j++) {
            FragB bhi, blo;
            wmma::load_matrix_sync(bhi, Whi + kk * 16 * LDA + wx * 32 + j * 16, LDA);
            wmma::load_matrix_sync(blo, Wlo + kk * 16 * LDA + wx * 32 + j * 16, LDA);
#pragma unroll
            for (int i = 0; i < 2; i++) {
                wmma::mma_sync(c[i][j], ahi[i], bhi, c[i][j]);
                wmma::mma_sync(c[i][j], ahi[i], blo, c[i][j]);
                wmma::mma_sync(c[i][j], alo[i], bhi, c[i][j]);
            }
        }
    }
}

// smem: Ahi+Alo (2*64*136*2 = 34816) + W (4*34816 = 139264) + stg (64*132*4 = 33792) = 207872
#define SM_A   0
#define SM_W   34816
#define SM_STG (34816 + 139264)
#define FG_SMEM (SM_STG + 64 * LDSG * 4)

__global__ void __launch_bounds__(256, 1)
k_fgemm(const float* __restrict__ A, const __nv_bfloat16* __restrict__ wimg,
        const float* __restrict__ b1, const float* __restrict__ b2,
        float* __restrict__ Z2) {
    extern __shared__ char sh[];
    __nv_bfloat16* Ahi = (__nv_bfloat16*)(sh + SM_A);
    __nv_bfloat16* Alo = Ahi + TR * LDA;
    __nv_bfloat16* Wt  = (__nv_bfloat16*)(sh + SM_W);
    float* stg = (float*)(sh + SM_STG);
    int tid = threadIdx.x;

    {   // weights once per block: 139264 B = 8704 uint4
        const uint4* wg = (const uint4*)wimg;
        uint4* wd = (uint4*)Wt;
#pragma unroll
        for (int i = 0; i < 34; i++) {
            int idx = tid + i * 256;
            if (idx < 8704) wd[idx] = wg[idx];
        }
    }

    int w = tid >> 5, wy = w >> 2, wx = w & 3;
    // register-resident stats: this thread owns (col = tid&127, half = tid>>7)
    int scol = tid & 127, shalf = tid >> 7;
    float bias2 = b2[scol];
    float s_acc = 0.f, q_acc = 0.f;

    __syncthreads();

    for (;;) {
        __syncthreads();                     // all warps done with previous tile's smem
        __shared__ int s_tile;
        if (tid == 0) s_tile = atomicAdd(&g_ticket, 1);
        __syncthreads();
        int t = s_tile;
        if (t >= NTILES) break;
        int row0 = t * TR;
        int live = NN - row0; if (live > TR) live = TR;

        // load + split A tile (64 x 128)
#pragma unroll
        for (int ii = 0; ii < 4; ii++) {
            int i = tid + ii * 256;          // 0..1023
            int r = i >> 4, c0 = (i & 15) << 3;
            float v[8];
            if (r < live) {
                float4 p = *(const float4*)&A[(size_t)(row0 + r) * 128 + c0];
                float4 q = *(const float4*)&A[(size_t)(row0 + r) * 128 + c0 + 4];
                v[0] = p.x; v[1] = p.y; v[2] = p.z; v[3] = p.w;
                v[4] = q.x; v[5] = q.y; v[6] = q.z; v[7] = q.w;
            } else {
#pragma unroll
                for (int e = 0; e < 8; e++) v[e] = 0.f;
            }
            B8 hi, lo;
#pragma unroll
            for (int e = 0; e < 8; e++) {
                __nv_bfloat16 h = __float2bfloat16_rn(v[e]);
                hi.b[e] = h;
                lo.b[e] = __float2bfloat16_rn(v[e] - __bfloat162float(h));
            }
            *(uint4*)&Ahi[r * LDA + c0] = hi.u;
            *(uint4*)&Alo[r * LDA + c0] = lo.u;
        }
        __syncthreads();

        FragC c[2][2];
        // GEMM1
        gemm_pass64(Ahi, Alo, Wt, Wt + TILE_E, c, wy, wx);
        __syncthreads();
#pragma unroll
        for (int i = 0; i < 2; i++)
#pragma unroll
            for (int j = 0; j < 2; j++)
                wmma::store_matrix_sync(stg + (wy * 32 + i * 16) * LDSG + wx * 32 + j * 16,
                                        c[i][j], LDSG, wmma::mem_row_major);
        __syncthreads();

        // z1 = relu(z1raw + b1) -> split -> Ahi/Alo
#pragma unroll
        for (int ii = 0; ii < 4; ii++) {
            int i = tid + ii * 256;
            int r = i >> 4, c0 = (i & 15) << 3;
            B8 hi, lo;
#pragma unroll
            for (int e = 0; e < 8; e++) {
                float v = fmaxf(stg[r * LDSG + c0 + e] + b1[c0 + e], 0.f);
                __nv_bfloat16 h = __float2bfloat16_rn(v);
                hi.b[e] = h;
                lo.b[e] = __float2bfloat16_rn(v - __bfloat162float(h));
            }
            *(uint4*)&Ahi[r * LDA + c0] = hi.u;
            *(uint4*)&Alo[r * LDA + c0] = lo.u;
        }
        __syncthreads();

        // GEMM2
        gemm_pass64(Ahi, Alo, Wt + 2 * TILE_E, Wt + 3 * TILE_E, c, wy, wx);
        __syncthreads();
#pragma unroll
        for (int i = 0; i < 2; i++)
#pragma unroll
            for (int j = 0; j < 2; j++)
                wmma::store_matrix_sync(stg + (wy * 32 + i * 16) * LDSG + wx * 32 + j * 16,
                                        c[i][j], LDSG, wmma::mem_row_major);
        __syncthreads();

        {   // z2 write: 4 threads/row
            int r = tid >> 2, q = tid & 3;
            if (r < live) {
                int c0 = q * 32;
#pragma unroll
                for (int g = 0; g < 8; g++) {
                    float4 v;
                    v.x = stg[r * LDSG + c0 + g * 4 + 0] + b2[c0 + g * 4 + 0];
                    v.y = stg[r * LDSG + c0 + g * 4 + 1] + b2[c0 + g * 4 + 1];
                    v.z = stg[r * LDSG + c0 + g * 4 + 2] + b2[c0 + g * 4 + 2];
                    v.w = stg[r * LDSG + c0 + g * 4 + 3] + b2[c0 + g * 4 + 3];
                    *(float4*)&Z2[(size_t)(row0 + r) * 128 + c0 + g * 4] = v;
                }
            }
        }
        {   // stats into registers
            for (int r = shalf; r < live; r += 2) {
                float v = stg[r * LDSG + scol] + bias2;
                s_acc += v; q_acc += v * v;
            }
        }
    }

    atomicAdd(&g_stats[scol], s_acc);
    atomicAdd(&g_stats[128 + scol], q_acc);
}

__global__ void k_finalize(const float* __restrict__ gamma, const float* __restrict__ beta) {
    int j = threadIdx.x;
    float mu = g_stats[j] * (1.0f / NN);
    float var = g_stats[128 + j] * (1.0f / NN) - mu * mu;
    float a = gamma[j] * rsqrtf(var + 1e-5f);
    g_scale[j] = a;
    g_shift[j] = beta[j] - mu * a;
    g_stats[j] = 0.f;            // ready for next layer
    g_stats[128 + j] = 0.f;
    if (j == 0) g_ticket = 0;
}

// ---------------- pooling (applies final BN) ----------------
__global__ void k_start(const int* __restrict__ batch) {
    int n = blockIdx.x * blockDim.x + threadIdx.x;
    if (n >= NN) return;
    int b = batch[n];
    if (n == 0) { for (int i = 0; i <= b; i++) g_start[i] = 0; }
    else {
        int p = batch[n - 1];
        for (int i = p + 1; i <= b; i++) g_start[i] = n;
    }
    if (n == NN - 1) { for (int i = b + 1; i <= NB; i++) g_start[i] = NN; }
}

__global__ void k_pool() {
    int b = blockIdx.x, j = threadIdx.x;
    int s = g_start[b], e = g_start[b + 1];
    float sc = g_scale[j], sf = g_shift[j];
    float sum = 0.f, mx = -3.402823466e38f;
    int n = s;
    for (; n + 2 <= e; n += 2) {
        float v0 = g_z2[(size_t)n * HD + j] * sc + sf;
        float v1 = g_z2[(size_t)(n + 1) * HD + j] * sc + sf;
        sum += v0 + v1;
        mx = fmaxf(mx, fmaxf(v0, v1));
    }
    for (; n < e; n++) {
        float v = g_z2[(size_t)n * HD + j] * sc + sf;
        sum += v; mx = fmaxf(mx, v);
    }
    int cnt = e - s;
    g_graph[b * 384 + j]       = cnt ? sum / (float)cnt : 0.f;
    g_graph[b * 384 + 128 + j] = cnt ? mx : 0.f;
    g_graph[b * 384 + 256 + j] = sum;
}

// ---------------- head ----------------
__global__ void k_head(const float* __restrict__ orders,
                       const float* __restrict__ oW1, const float* __restrict__ ob1,
                       const float* __restrict__ oW2, const float* __restrict__ ob2,
                       const float* __restrict__ sW1, const float* __restrict__ sb1,
                       const float* __restrict__ sW2, const float* __restrict__ sb2,
                       const float* __restrict__ sW3, const float* __restrict__ sb3,
                       float* __restrict__ out) {
    extern __shared__ float fsh[];
    float* comb  = fsh;                      // 32*512
    float* t_all = comb + 32 * 512;          // 32*128
    float* s2m   = t_all + 32 * 128;         // 32*68
    float* ords  = s2m + 32 * 68;            // 32*33
    int b = blockIdx.x, tid = threadIdx.x;

    for (int idx = tid; idx < 32 * 384; idx += 128) {
        int o = idx / 384, k = idx - o * 384;
        comb[o * 512 + k] = g_graph[b * 384 + k];
    }
    for (int idx = tid; idx < 32 * 32; idx += 128) {
        int o = idx >> 5, k = idx & 31;
        ords[o * 33 + k] = orders[(b * 32 + o) * 32 + k];
    }
    __syncthreads();

    int tcol = tid & 31, tord = tid >> 5;

    {   // t = relu(ords @ oW1 + ob1)
        float4 bc = *(const float4*)&ob1[tcol * 4];
        float acc[8][4];
#pragma unroll
        for (int i = 0; i < 8; i++) { acc[i][0] = bc.x; acc[i][1] = bc.y; acc[i][2] = bc.z; acc[i][3] = bc.w; }
#pragma unroll
        for (int k = 0; k < 32; k++) {
            float4 w = *(const float4*)&oW1[k * 128 + tcol * 4];
#pragma unroll
            for (int i = 0; i < 8; i++) {
                float a = ords[(tord * 8 + i) * 33 + k];
                acc[i][0] += a * w.x; acc[i][1] += a * w.y;
                acc[i][2] += a * w.z; acc[i][3] += a * w.w;
            }
        }
#pragma unroll
        for (int i = 0; i < 8; i++)
            *(float4*)&t_all[(tord * 8 + i) * 128 + tcol * 4] =
                make_float4(fmaxf(acc[i][0], 0.f), fmaxf(acc[i][1], 0.f),
                            fmaxf(acc[i][2], 0.f), fmaxf(acc[i][3], 0.f));
    }
    __syncthreads();

    {   // oe = t @ oW2 + ob2 -> comb[:,384:]
        float4 bc = *(const float4*)&ob2[tcol * 4];
        float acc[8][4];
#pragma unroll
        for (int i = 0; i < 8; i++) { acc[i][0] = bc.x; acc[i][1] = bc.y; acc[i][2] = bc.z; acc[i][3] = bc.w; }
#pragma unroll 4
        for (int k = 0; k < 128; k++) {
            float4 w = *(const float4*)&oW2[k * 128 + tcol * 4];
#pragma unroll
            for (int i = 0; i < 8; i++) {
                float a = t_all[(tord * 8 + i) * 128 + k];
                acc[i][0] += a * w.x; acc[i][1] += a * w.y;
                acc[i][2] += a * w.z; acc[i][3] += a * w.w;
            }
        }
        __syncthreads();
#pragma unroll
        for (int i = 0; i < 8; i++)
            *(float4*)&comb[(tord * 8 + i) * 512 + 384 + tcol * 4] =
                make_float4(acc[i][0], acc[i][1], acc[i][2], acc[i][3]);
    }
    __syncthreads();

    {   // s1 = relu(comb @ sW1 + sb1)
        float4 bc = *(const float4*)&sb1[tcol * 4];
        float acc[8][4];
#pragma unroll
        for (int i = 0; i < 8; i++) { acc[i][0] = bc.x; acc[i][1] = bc.y; acc[i][2] = bc.z; acc[i][3] = bc.w; }
#pragma unroll 4
        for (int k = 0; k < 512; k++) {
            float4 w = *(const float4*)&sW1[k * 128 + tcol * 4];
#pragma unroll
            for (int i = 0; i < 8; i++) {
                float a = comb[(tord * 8 + i) * 512 + k];
                acc[i][0] += a * w.x; acc[i][1] += a * w.y;
                acc[i][2] += a * w.z; acc[i][3] += a * w.w;
            }
        }
#pragma unroll
        for (int i = 0; i < 8; i++)
            *(float4*)&t_all[(tord * 8 + i) * 128 + tcol * 4] =
                make_float4(fmaxf(acc[i][0], 0.f), fmaxf(acc[i][1], 0.f),
                            fmaxf(acc[i][2], 0.f), fmaxf(acc[i][3], 0.f));
    }
    __syncthreads();

    {   // s2 = relu(s1 @ sW2 + sb2)
        int tc2 = tid & 15, to2 = tid >> 4;
        float4 bc = *(const float4*)&sb2[tc2 * 4];
        float acc[4][4];
#pragma unroll
        for (int i = 0; i < 4; i++) { acc[i][0] = bc.x; acc[i][1] = bc.y; acc[i][2] = bc.z; acc[i][3] = bc.w; }
#pragma unroll 4
        for (int k = 0; k < 128; k++) {
            float4 w = *(const float4*)&sW2[k * 64 + tc2 * 4];
#pragma unroll
            for (int i = 0; i < 4; i++) {
                float a = t_all[(to2 * 4 + i) * 128 + k];
                acc[i][0] += a * w.x; acc[i][1] += a * w.y;
                acc[i][2] += a * w.z; acc[i][3] += a * w.w;
            }
        }
#pragma unroll
        for (int i = 0; i < 4; i++)
            *(float4*)&s2m[(to2 * 4 + i) * 68 + tc2 * 4] =
                make_float4(fmaxf(acc[i][0], 0.f), fmaxf(acc[i][1], 0.f),
                            fmaxf(acc[i][2], 0.f), fmaxf(acc[i][3], 0.f));
    }
    __syncthreads();

    if (tid < 32) {
        float acc = sb3[0];
#pragma unroll 8
        for (int k = 0; k < 64; k++) acc += s2m[tid * 68 + k] * sW3[k];
        out[b * 32 + tid] = acc;
    }
}

// ---------------- launch ----------------
extern "C" void kernel_launch(void* const* d_in, const int* in_sizes, int n_in,
                              void* d_out, int out_size) {
    const float* x      = (const float*)d_in[0];
    const int*   ei     = (const int*)d_in[1];
    const float* orders = (const float*)d_in[2];
    const int*   batch  = (const int*)d_in[3];
    const float* gW1    = (const float*)d_in[4];
    const float* gb1    = (const float*)d_in[5];
    const float* gW2    = (const float*)d_in[6];
    const float* gb2    = (const float*)d_in[7];
    const float* gamma  = (const float*)d_in[8];
    const float* beta   = (const float*)d_in[9];
    const float* oW1    = (const float*)d_in[10];
    const float* ob1    = (const float*)d_in[11];
    const float* oW2    = (const float*)d_in[12];
    const float* ob2    = (const float*)d_in[13];
    const float* sW1    = (const float*)d_in[14];
    const float* sb1    = (const float*)d_in[15];
    const float* sW2    = (const float*)d_in[16];
    const float* sb2    = (const float*)d_in[17];
    const float* sW3    = (const float*)d_in[18];
    const float* sb3    = (const float*)d_in[19];
    float* out = (float*)d_out;

    void *p_agg, *p_z2, *p_wimg;
    cudaGetSymbolAddress(&p_agg,  g_agg);
    cudaGetSymbolAddress(&p_z2,   g_z2);
    cudaGetSymbolAddress(&p_wimg, g_wimg);

    size_t head_smem = (size_t)(32 * 512 + 32 * 128 + 32 * 68 + 32 * 33) * 4;
    cudaFuncSetAttribute(k_head, cudaFuncAttributeMaxDynamicSharedMemorySize, (int)head_smem);
    cudaFuncSetAttribute(k_fgemm, cudaFuncAttributeMaxDynamicSharedMemorySize, FG_SMEM);

    // launches 1..5: init + CSR + weight prep  (launch #6 = k_agg<0> for ncu)
    k_zero<<<(NN + 1 + 255) / 256, 256>>>();
    k_hist<<<(NE + 255) / 256, 256>>>(ei);
    k_scan<<<1, 1024>>>();
    k_fillcsr<<<(NE + 255) / 256, 256>>>(ei);
    k_prepw<<<(NL * 2 * 16384 + 255) / 256, 256>>>(gW1, gW2);

    for (int l = 0; l < NL; l++) {
        if (l == 0) k_agg<0><<<(NN * 32 + 255) / 256, 256>>>(x);
        else        k_agg<1><<<(NN * 32 + 255) / 256, 256>>>((const float*)p_z2);
        k_fgemm<<<148, 256, FG_SMEM>>>((const float*)p_agg,
                                       (const __nv_bfloat16*)p_wimg + (size_t)l * 4 * TILE_E,
                                       gb1 + l * HD, gb2 + l * HD, (float*)p_z2);
        k_finalize<<<1, 128>>>(gamma + l * HD, beta + l * HD);
    }

    k_start<<<(NN + 255) / 256, 256>>>(batch);
    k_pool<<<NB, 128>>>();
    k_head<<<NB, 128, head_smem>>>(orders, oW1, ob1, oW2, ob2,
                                   sW1, sb1, sW2, sb2, sW3, sb3, out);
}